// round 3
// baseline (speedup 1.0000x reference)
#include <cuda_runtime.h>
#include <cuda_bf16.h>
#include <cstdint>

// Problem constants
#define BB   4
#define C3   256
#define H3   48
#define L3   (H3*H3)          // 2304
#define C2   128
#define H2   96
#define L2n  (H2*H2)          // 9216
#define C1   64
#define H1   192
#define L1n  (H1*H1)          // 36864
#define EPSN 1e-12f

#define KK   1536             // 6 * 256 (3-way bf16 split, 6 product segments)

// ---------------- scratch (static device globals; no allocation) -------------
__device__ float g_P[(size_t)BB * L3 * L3];          // [b][lq][lk]  ~85MB
__device__ __align__(256) __nv_bfloat16 g_A2[(size_t)BB * L3 * KK];  // [b][m][k'']
__device__ __align__(256) __nv_bfloat16 g_B2[(size_t)BB * L3 * KK];  // [b][n][k'']
__device__ float g_cl3T[(size_t)BB * L3 * C3];       // [b][pix][c]
__device__ float g_cl2T[(size_t)BB * L2n * C2];
__device__ float g_cl1T[(size_t)BB * L1n * C1];
__device__ float g_sq[2][BB * L3];                    // per-pixel sq-norm: 0=img 1=ref
__device__ float g_nrm[2][BB * L3];                   // 0: nq(img) norm, 1: 1/nk(ref)
__device__ int   g_idx[BB * L3];                      // argmax index per query

// ---------------- cp.async helpers -------------------------------------------
__device__ __forceinline__ void cp_async16(uint32_t smem, const void* gmem) {
    asm volatile("cp.async.cg.shared.global [%0], [%1], 16;\n" :: "r"(smem), "l"(gmem));
}
__device__ __forceinline__ void cp_commit() {
    asm volatile("cp.async.commit_group;\n" ::: "memory");
}
__device__ __forceinline__ void cp_wait0() {
    asm volatile("cp.async.wait_group 0;\n" ::: "memory");
}

// ---------------- 1) per-pixel squared norms ---------------------------------
__global__ void sqsum_kernel(const float* __restrict__ img, const float* __restrict__ ref) {
    int l = blockIdx.x * 256 + threadIdx.x;           // 0..2303
    int b = blockIdx.y;
    int which = blockIdx.z;                           // 0=img 1=ref
    const float* src = (which == 0) ? img : ref;
    src += (size_t)b * C3 * L3 + l;
    float s = 0.f;
    #pragma unroll 4
    for (int c = 0; c < C3; c++) {
        float v = src[(size_t)c * L3];
        s += v * v;
    }
    g_sq[which][b * L3 + l] = s;
}

// ---------------- 2) 3x3 box-sum -> patch norm -------------------------------
__global__ void boxnorm_kernel() {
    int l = blockIdx.x * 256 + threadIdx.x;
    int b = blockIdx.y;
    int which = blockIdx.z;
    int y = l / H3, x = l % H3;
    const float* s = &g_sq[which][b * L3];
    float acc = 0.f;
    #pragma unroll
    for (int dy = -1; dy <= 1; dy++) {
        int yy = y + dy;
        if ((unsigned)yy >= H3) continue;
        #pragma unroll
        for (int dx = -1; dx <= 1; dx++) {
            int xx = x + dx;
            if ((unsigned)xx >= H3) continue;
            acc += s[yy * H3 + xx];
        }
    }
    float n = fmaxf(sqrtf(acc), EPSN);
    g_nrm[which][b * L3 + l] = (which == 1) ? (1.0f / n) : n;
}

// ---------------- 3) transpose cl_ref to channel-last ------------------------
__global__ void transpose_kernel(const float* __restrict__ src, int C, int L, int sel) {
    float* dst = (sel == 0) ? g_cl3T : (sel == 1) ? g_cl2T : g_cl1T;
    __shared__ float tile[32][33];
    int l0 = blockIdx.x * 32, c0 = blockIdx.y * 32, b = blockIdx.z;
    const float* s = src + (size_t)b * C * L;
    float* d = dst + (size_t)b * L * C;
    #pragma unroll
    for (int i = threadIdx.y; i < 32; i += 8)
        tile[i][threadIdx.x] = s[(size_t)(c0 + i) * L + l0 + threadIdx.x];
    __syncthreads();
    #pragma unroll
    for (int i = threadIdx.y; i < 32; i += 8)
        d[(size_t)(l0 + i) * C + c0 + threadIdx.x] = tile[threadIdx.x][i];
}

// ---------------- 3b) 3-way bf16 split + transpose ---------------------------
// in: [k][m] fp32 (m-contig)  ->  out: [m][1536] bf16 (k-contig), 6 segments:
//   A'' segs: [h, h, m, h, l, m]     B'' segs: [h, m, h, l, h, m]
// product pairs along k'': (h,h)(h,m)(m,h)(h,l)(l,h)(m,m)
__global__ void split3_kernel(const float* __restrict__ img, const float* __restrict__ ref) {
    int b = blockIdx.z & 3;
    int which = blockIdx.z >> 2;                 // 0=img->A2  1=ref->B2
    const float* src = (which == 0) ? img : ref;
    __nv_bfloat16* dst = (which == 0) ? g_A2 : g_B2;
    __shared__ float tile[32][33];
    int m0 = blockIdx.x * 32, k0 = blockIdx.y * 32;
    src += (size_t)b * C3 * L3;
    int tx = threadIdx.x, ty = threadIdx.y;
    #pragma unroll
    for (int i = ty; i < 32; i += 8)
        tile[i][tx] = src[(size_t)(k0 + i) * L3 + m0 + tx];   // tile[k_local][m_local]
    __syncthreads();
    #pragma unroll
    for (int i = ty; i < 32; i += 8) {
        int m = m0 + i, k = k0 + tx;
        float x = tile[tx][i];
        __nv_bfloat16 h  = __float2bfloat16_rn(x);
        float r1 = x - __bfloat162float(h);
        __nv_bfloat16 mm = __float2bfloat16_rn(r1);
        float r2 = r1 - __bfloat162float(mm);
        __nv_bfloat16 lo = __float2bfloat16_rn(r2);
        __nv_bfloat16* row = dst + ((size_t)b * L3 + m) * KK;
        if (which == 0) {
            row[k]        = h;  row[256  + k] = h;  row[512  + k] = mm;
            row[768 + k]  = h;  row[1024 + k] = lo; row[1280 + k] = mm;
        } else {
            row[k]        = h;  row[256  + k] = mm; row[512  + k] = h;
            row[768 + k]  = lo; row[1024 + k] = h;  row[1280 + k] = mm;
        }
    }
}

// ---------------- 4) bf16 tensor-core GEMM: P = A'' * B''^T ------------------
// Block 128x128, 8 warps (2x4), warp tile 64x32, mma.m16n8k16, BK=32,
// double-buffered cp.async. Row pad 40 halves -> conflict-free LDS.32 frags.
#define BKH 32
#define PADH 40
__global__ void __launch_bounds__(256, 2) gemm_bf16_kernel() {
    const int b  = blockIdx.z;
    const int m0 = blockIdx.y * 128;
    const int n0 = blockIdx.x * 128;
    const __nv_bfloat16* Ab = g_A2 + (size_t)b * L3 * KK;
    const __nv_bfloat16* Bb = g_B2 + (size_t)b * L3 * KK;
    float* Cc = g_P + (size_t)b * L3 * L3;

    __shared__ __align__(16) __nv_bfloat16 As[2][128][PADH];
    __shared__ __align__(16) __nv_bfloat16 Bs[2][128][PADH];

    const int tid  = threadIdx.x;
    const int lane = tid & 31;
    const int warp = tid >> 5;
    const int wm = warp >> 2;            // 0..1
    const int wn = warp & 3;             // 0..3
    const int g  = lane >> 2;            // 0..7
    const int t2 = (lane & 3) * 2;       // 0,2,4,6

    // cp.async mapping: 2 chunks/thread/tile: chunk=q*256+tid -> row=chunk/4, c16=chunk%4
    const int lrow0 = tid >> 2;          // rows 0..63   (q=0)
    const int lrow1 = 64 + (tid >> 2);   // rows 64..127 (q=1)
    const int lch   = (tid & 3) * 8;     // half offset 0,8,16,24

    const __nv_bfloat16* gA0 = Ab + (size_t)(m0 + lrow0) * KK + lch;
    const __nv_bfloat16* gA1 = Ab + (size_t)(m0 + lrow1) * KK + lch;
    const __nv_bfloat16* gB0 = Bb + (size_t)(n0 + lrow0) * KK + lch;
    const __nv_bfloat16* gB1 = Bb + (size_t)(n0 + lrow1) * KK + lch;

    uint32_t sA0[2], sA1[2], sB0[2], sB1[2];
    #pragma unroll
    for (int u = 0; u < 2; u++) {
        sA0[u] = (uint32_t)__cvta_generic_to_shared(&As[u][lrow0][lch]);
        sA1[u] = (uint32_t)__cvta_generic_to_shared(&As[u][lrow1][lch]);
        sB0[u] = (uint32_t)__cvta_generic_to_shared(&Bs[u][lrow0][lch]);
        sB1[u] = (uint32_t)__cvta_generic_to_shared(&Bs[u][lrow1][lch]);
    }

    float acc[16][4];
    #pragma unroll
    for (int i = 0; i < 16; i++)
        #pragma unroll
        for (int j = 0; j < 4; j++) acc[i][j] = 0.f;

    // prefetch stage 0
    cp_async16(sA0[0], gA0); cp_async16(sA1[0], gA1);
    cp_async16(sB0[0], gB0); cp_async16(sB1[0], gB1);
    cp_commit();

    const int NSTAGES = KK / BKH;   // 48
    int buf = 0;
    for (int ks = 0; ks < NSTAGES; ks++) {
        cp_wait0();
        __syncthreads();

        if (ks + 1 < NSTAGES) {
            size_t off = (size_t)(ks + 1) * BKH;
            int nb = buf ^ 1;
            cp_async16(sA0[nb], gA0 + off); cp_async16(sA1[nb], gA1 + off);
            cp_async16(sB0[nb], gB0 + off); cp_async16(sB1[nb], gB1 + off);
            cp_commit();
        }

        #pragma unroll
        for (int half = 0; half < 2; half++) {
            const int kb = half * 16;
            uint32_t a[4][4], bf[4][2];
            #pragma unroll
            for (int mi = 0; mi < 4; mi++) {
                int rm = wm * 64 + mi * 16 + g;
                a[mi][0] = *(const uint32_t*)&As[buf][rm    ][kb + t2];
                a[mi][1] = *(const uint32_t*)&As[buf][rm + 8][kb + t2];
                a[mi][2] = *(const uint32_t*)&As[buf][rm    ][kb + t2 + 8];
                a[mi][3] = *(const uint32_t*)&As[buf][rm + 8][kb + t2 + 8];
            }
            #pragma unroll
            for (int ni = 0; ni < 4; ni++) {
                int rn = wn * 32 + ni * 8 + g;
                bf[ni][0] = *(const uint32_t*)&Bs[buf][rn][kb + t2];
                bf[ni][1] = *(const uint32_t*)&Bs[buf][rn][kb + t2 + 8];
            }
            #pragma unroll
            for (int mi = 0; mi < 4; mi++)
                #pragma unroll
                for (int ni = 0; ni < 4; ni++) {
                    float* c = acc[mi * 4 + ni];
                    asm volatile(
                        "mma.sync.aligned.m16n8k16.row.col.f32.bf16.bf16.f32 "
                        "{%0,%1,%2,%3},{%4,%5,%6,%7},{%8,%9},{%0,%1,%2,%3};\n"
                        : "+f"(c[0]), "+f"(c[1]), "+f"(c[2]), "+f"(c[3])
                        : "r"(a[mi][0]), "r"(a[mi][1]), "r"(a[mi][2]), "r"(a[mi][3]),
                          "r"(bf[ni][0]), "r"(bf[ni][1]));
                }
        }
        buf ^= 1;
    }

    // epilogue: direct float2 stores
    #pragma unroll
    for (int mi = 0; mi < 4; mi++) {
        #pragma unroll
        for (int ni = 0; ni < 4; ni++) {
            int m = m0 + wm * 64 + mi * 16 + g;
            int n = n0 + wn * 32 + ni * 8 + t2;
            float* c = acc[mi * 4 + ni];
            float* p = Cc + (size_t)m * L3 + n;
            *(float2*)p              = make_float2(c[0], c[1]);
            *(float2*)(p + 8 * L3)   = make_float2(c[2], c[3]);
        }
    }
}

// ---------------- 5) shifted-sum + max/argmax over lk ------------------------
__global__ void maxarg_kernel(float* __restrict__ outS) {
    int b = blockIdx.y, lq = blockIdx.x;
    int yq = lq / H3, xq = lq % H3;
    const float* base = g_P + (size_t)b * L3 * L3;

    int  rowOff[9];
    bool qv[9];
    #pragma unroll
    for (int t = 0; t < 9; t++) {
        int di = t / 3 - 1, dj = t % 3 - 1;
        int y2 = yq + di, x2 = xq + dj;
        bool v = ((unsigned)y2 < H3) && ((unsigned)x2 < H3);
        qv[t] = v;
        int d = di * H3 + dj;
        rowOff[t] = v ? (lq + d) * L3 + d : 0;
    }
    const float* rnk = &g_nrm[1][b * L3];   // reciprocal key norms

    float best = -1e30f; int bi = 0;
    for (int lk = threadIdx.x; lk < L3; lk += 256) {
        int yk = lk / H3, xk = lk % H3;
        float s = 0.f;
        #pragma unroll
        for (int t = 0; t < 9; t++) {
            int di = t / 3 - 1, dj = t % 3 - 1;
            if (qv[t] && ((unsigned)(yk + di) < H3) && ((unsigned)(xk + dj) < H3))
                s += base[rowOff[t] + lk];
        }
        float sc = s * rnk[lk];
        if (sc > best) { best = sc; bi = lk; }
    }

    __shared__ float sv[256];
    __shared__ int   si[256];
    sv[threadIdx.x] = best; si[threadIdx.x] = bi;
    __syncthreads();
    for (int st = 128; st > 0; st >>= 1) {
        if (threadIdx.x < st) {
            float o = sv[threadIdx.x + st]; int oi = si[threadIdx.x + st];
            if (o > sv[threadIdx.x] || (o == sv[threadIdx.x] && oi < si[threadIdx.x])) {
                sv[threadIdx.x] = o; si[threadIdx.x] = oi;
            }
        }
        __syncthreads();
    }
    if (threadIdx.x == 0) {
        g_idx[b * L3 + lq] = si[0];
        outS[b * L3 + lq]  = sv[0] / g_nrm[0][b * L3 + lq];
    }
}

// ---------------- 6) fused gather + fold-normalize ---------------------------
__global__ void transfer_kernel(float* __restrict__ out, int C, int W, int s, int sel) {
    const float* clT = (sel == 0) ? g_cl3T : (sel == 1) ? g_cl2T : g_cl1T;
    __shared__ float acc[12288];                 // C*W floats == 48KB for all levels
    int b = blockIdx.y, y = blockIdx.x;
    int tid = threadIdx.x;
    int cid  = tid % C;
    int xsub = tid / C;
    int ppp  = 256 / C;                          // pixels handled in parallel

    int tyq = y / s;
    int yqs[3]; int nvy = 0;
    #pragma unroll
    for (int d = -1; d <= 1; d++) {
        int yq = tyq + d;
        if (0 <= yq && yq < H3) yqs[nvy++] = yq;
    }
    const int* idxb = g_idx + b * L3;
    size_t clb = (size_t)b * W * W * C;

    for (int x0 = 0; x0 < W; x0 += ppp) {
        int x = x0 + xsub;
        int txq = x / s;
        float sum = 0.f; int cnt = 0;
        for (int a = 0; a < nvy; a++) {
            int yq = yqs[a];
            #pragma unroll
            for (int d = -1; d <= 1; d++) {
                int xq = txq + d;
                if ((unsigned)xq >= H3) continue;
                cnt++;
                int idx = idxb[yq * H3 + xq];
                int yk = idx / H3, xk = idx % H3;
                int ys = y + s * (yk - yq);
                int xs = x + s * (xk - xq);
                if ((unsigned)ys < (unsigned)W && (unsigned)xs < (unsigned)W)
                    sum += clT[clb + ((size_t)ys * W + xs) * C + cid];
            }
        }
        acc[cid * W + x] = sum / (float)cnt;
    }
    __syncthreads();

    size_t ob = (size_t)b * C * W * W + (size_t)y * W;
    for (int i = tid; i < C * W; i += 256) {
        int c = i / W, x = i % W;
        out[ob + (size_t)c * W * W + x] = acc[i];
    }
}

// ---------------- launch ------------------------------------------------------
extern "C" void kernel_launch(void* const* d_in, const int* in_sizes, int n_in,
                              void* d_out, int out_size) {
    const float* img = (const float*)d_in[0];   // dh_img_lv3 [4,256,48,48]
    const float* ref = (const float*)d_in[1];   // dh_ref_lv3 [4,256,48,48]
    const float* cl1 = (const float*)d_in[2];   // cl_ref_lv1 [4,64,192,192]
    const float* cl2 = (const float*)d_in[3];   // cl_ref_lv2 [4,128,96,96]
    const float* cl3 = (const float*)d_in[4];   // cl_ref_lv3 [4,256,48,48]

    float* outS  = (float*)d_out;               // [4,1,48,48]
    float* outT3 = outS  + BB * L3;             // [4,256,48,48]
    float* outT2 = outT3 + (size_t)BB * C3 * L3;    // [4,128,96,96]
    float* outT1 = outT2 + (size_t)BB * C2 * L2n;   // [4,64,192,192]

    sqsum_kernel  <<<dim3(9, BB, 2), 256>>>(img, ref);
    boxnorm_kernel<<<dim3(9, BB, 2), 256>>>();

    split3_kernel<<<dim3(L3 / 32, C3 / 32, BB * 2), dim3(32, 8)>>>(img, ref);

    transpose_kernel<<<dim3(L3  / 32, C3 / 32, BB), dim3(32, 8)>>>(cl3, C3, L3,  0);
    transpose_kernel<<<dim3(L2n / 32, C2 / 32, BB), dim3(32, 8)>>>(cl2, C2, L2n, 1);
    transpose_kernel<<<dim3(L1n / 32, C1 / 32, BB), dim3(32, 8)>>>(cl1, C1, L1n, 2);

    gemm_bf16_kernel<<<dim3(L3 / 128, L3 / 128, BB), 256>>>();

    maxarg_kernel<<<dim3(L3, BB), 256>>>(outS);

    transfer_kernel<<<dim3(H3, BB), 256>>>(outT3, C3, H3, 1, 0);
    transfer_kernel<<<dim3(H2, BB), 256>>>(outT2, C2, H2, 2, 1);
    transfer_kernel<<<dim3(H1, BB), 256>>>(outT1, C1, H1, 4, 2);
}

// round 4
// speedup vs baseline: 1.0912x; 1.0912x over previous
#include <cuda_runtime.h>
#include <cuda_bf16.h>
#include <cstdint>

// Problem constants
#define BB   4
#define C3   256
#define H3   48
#define L3   (H3*H3)          // 2304
#define C2   128
#define H2   96
#define L2n  (H2*H2)          // 9216
#define C1   64
#define H1   192
#define L1n  (H1*H1)          // 36864
#define EPSN 1e-12f

// ---------------- scratch (static device globals; no allocation) -------------
__device__ float g_P[(size_t)BB * L3 * L3];          // [b][lq][lk]  ~85MB
__device__ float g_cl3T[(size_t)BB * L3 * C3];       // [b][pix][c]
__device__ float g_cl2T[(size_t)BB * L2n * C2];
__device__ float g_cl1T[(size_t)BB * L1n * C1];
__device__ float g_sq[2][BB * L3];                    // per-pixel sq-norm: 0=img 1=ref
__device__ float g_nrm[2][BB * L3];                   // 0: nq(img) norm, 1: 1/nk(ref)
__device__ int   g_idx[BB * L3];                      // argmax index per query

// ---------------- cp.async helpers -------------------------------------------
__device__ __forceinline__ void cp_async16(uint32_t smem, const void* gmem) {
    asm volatile("cp.async.cg.shared.global [%0], [%1], 16;\n" :: "r"(smem), "l"(gmem));
}
__device__ __forceinline__ void cp_commit() {
    asm volatile("cp.async.commit_group;\n" ::: "memory");
}
__device__ __forceinline__ void cp_wait0() {
    asm volatile("cp.async.wait_group 0;\n" ::: "memory");
}
__device__ __forceinline__ float cvt_tf32(float x) {
    float r;
    asm("cvt.rna.tf32.f32 %0, %1;" : "=f"(r) : "f"(x));
    return r;
}

// ---------------- 1) per-pixel squared norms ---------------------------------
__global__ void sqsum_kernel(const float* __restrict__ img, const float* __restrict__ ref) {
    int l = blockIdx.x * 256 + threadIdx.x;           // 0..2303
    int b = blockIdx.y;
    int which = blockIdx.z;                           // 0=img 1=ref
    const float* src = (which == 0) ? img : ref;
    src += (size_t)b * C3 * L3 + l;
    float s = 0.f;
    #pragma unroll 4
    for (int c = 0; c < C3; c++) {
        float v = src[(size_t)c * L3];
        s += v * v;
    }
    g_sq[which][b * L3 + l] = s;
}

// ---------------- 2) 3x3 box-sum -> patch norm -------------------------------
__global__ void boxnorm_kernel() {
    int l = blockIdx.x * 256 + threadIdx.x;
    int b = blockIdx.y;
    int which = blockIdx.z;
    int y = l / H3, x = l % H3;
    const float* s = &g_sq[which][b * L3];
    float acc = 0.f;
    #pragma unroll
    for (int dy = -1; dy <= 1; dy++) {
        int yy = y + dy;
        if ((unsigned)yy >= H3) continue;
        #pragma unroll
        for (int dx = -1; dx <= 1; dx++) {
            int xx = x + dx;
            if ((unsigned)xx >= H3) continue;
            acc += s[yy * H3 + xx];
        }
    }
    float n = fmaxf(sqrtf(acc), EPSN);
    g_nrm[which][b * L3 + l] = (which == 1) ? (1.0f / n) : n;
}

// ---------------- 3) transpose cl_ref to channel-last ------------------------
__global__ void transpose_kernel(const float* __restrict__ src, int C, int L, int sel) {
    float* dst = (sel == 0) ? g_cl3T : (sel == 1) ? g_cl2T : g_cl1T;
    __shared__ float tile[32][33];
    int l0 = blockIdx.x * 32, c0 = blockIdx.y * 32, b = blockIdx.z;
    const float* s = src + (size_t)b * C * L;
    float* d = dst + (size_t)b * L * C;
    #pragma unroll
    for (int i = threadIdx.y; i < 32; i += 8)
        tile[i][threadIdx.x] = s[(size_t)(c0 + i) * L + l0 + threadIdx.x];
    __syncthreads();
    #pragma unroll
    for (int i = threadIdx.y; i < 32; i += 8)
        d[(size_t)(l0 + i) * C + c0 + threadIdx.x] = tile[threadIdx.x][i];
}

// ---------------- 4) tf32 tensor-core GEMM with in-register 2-limb split -----
// P[b][lq][lk] = sum_c img[c][lq]*ref[c][lk].  Block 128x128, 8 warps (2x4),
// warp tile 64x32, mma.m16n8k8.tf32, 3 limb products (hh, hl, lh).
// smem tiles fp32 [k][m] with row stride 136 words (bank-conflict-free frags).
#define BKF 16
#define SST 136
__global__ void __launch_bounds__(256, 2) gemm_tf32_kernel(const float* __restrict__ img,
                                                           const float* __restrict__ ref) {
    const int b  = blockIdx.z;
    const int m0 = blockIdx.y * 128;
    const int n0 = blockIdx.x * 128;
    const float* A  = img + (size_t)b * C3 * L3;   // [k][m]
    const float* Bm = ref + (size_t)b * C3 * L3;   // [k][n]
    float* Cc = g_P + (size_t)b * L3 * L3;

    __shared__ __align__(16) float As[2][BKF * SST];
    __shared__ __align__(16) float Bs[2][BKF * SST];

    const int tid  = threadIdx.x;
    const int lane = tid & 31;
    const int warp = tid >> 5;
    const int wm = warp >> 2;            // 0..1
    const int wn = warp & 3;             // 0..3
    const int g  = lane >> 2;            // 0..7
    const int c4 = lane & 3;             // 0..3
    const int t2 = c4 * 2;

    // cp.async mapping: 2 chunks of 16B per thread per tile
    const int kr = tid >> 5;             // 0..7  (second chunk: +8)
    const int cc = (tid & 31) * 4;       // fp32 col 0..124

    const float* gA0 = A  + (size_t)kr * L3 + m0 + cc;
    const float* gA1 = A  + (size_t)(kr + 8) * L3 + m0 + cc;
    const float* gB0 = Bm + (size_t)kr * L3 + n0 + cc;
    const float* gB1 = Bm + (size_t)(kr + 8) * L3 + n0 + cc;
    const size_t kstep = (size_t)BKF * L3;

    uint32_t sA0[2], sA1[2], sB0[2], sB1[2];
    #pragma unroll
    for (int u = 0; u < 2; u++) {
        sA0[u] = (uint32_t)__cvta_generic_to_shared(&As[u][kr * SST + cc]);
        sA1[u] = (uint32_t)__cvta_generic_to_shared(&As[u][(kr + 8) * SST + cc]);
        sB0[u] = (uint32_t)__cvta_generic_to_shared(&Bs[u][kr * SST + cc]);
        sB1[u] = (uint32_t)__cvta_generic_to_shared(&Bs[u][(kr + 8) * SST + cc]);
    }

    float acc[16][4];
    #pragma unroll
    for (int i = 0; i < 16; i++)
        #pragma unroll
        for (int j = 0; j < 4; j++) acc[i][j] = 0.f;

    cp_async16(sA0[0], gA0); cp_async16(sA1[0], gA1);
    cp_async16(sB0[0], gB0); cp_async16(sB1[0], gB1);
    cp_commit();

    int buf = 0;
    for (int k0 = 0; k0 < C3; k0 += BKF) {
        cp_wait0();
        __syncthreads();

        if (k0 + BKF < C3) {
            size_t off = (size_t)((k0 + BKF) / BKF) * kstep;
            int nb = buf ^ 1;
            cp_async16(sA0[nb], gA0 + off); cp_async16(sA1[nb], gA1 + off);
            cp_async16(sB0[nb], gB0 + off); cp_async16(sB1[nb], gB1 + off);
            cp_commit();
        }

        const float* Ab = As[buf];
        const float* Bb = Bs[buf];

        #pragma unroll
        for (int half = 0; half < 2; half++) {
            const int kb = half * 8;

            // B fragments for all 4 ni (shared across mi): b0=[kb+c4][rn], b1=[kb+c4+4][rn]
            float bh[4][2], bl[4][2];
            #pragma unroll
            for (int ni = 0; ni < 4; ni++) {
                int rn = wn * 32 + ni * 8 + g;
                #pragma unroll
                for (int r = 0; r < 2; r++) {
                    float x = Bb[(kb + c4 + r * 4) * SST + rn];
                    float h = cvt_tf32(x);
                    bh[ni][r] = h;
                    bl[ni][r] = cvt_tf32(x - h);
                }
            }

            #pragma unroll
            for (int mi = 0; mi < 4; mi++) {
                int rm = wm * 64 + mi * 16 + g;
                float ah[4], al[4];
                {
                    float x0 = Ab[(kb + c4)     * SST + rm];
                    float x1 = Ab[(kb + c4)     * SST + rm + 8];
                    float x2 = Ab[(kb + c4 + 4) * SST + rm];
                    float x3 = Ab[(kb + c4 + 4) * SST + rm + 8];
                    ah[0] = cvt_tf32(x0); al[0] = cvt_tf32(x0 - ah[0]);
                    ah[1] = cvt_tf32(x1); al[1] = cvt_tf32(x1 - ah[1]);
                    ah[2] = cvt_tf32(x2); al[2] = cvt_tf32(x2 - ah[2]);
                    ah[3] = cvt_tf32(x3); al[3] = cvt_tf32(x3 - ah[3]);
                }
                #pragma unroll
                for (int ni = 0; ni < 4; ni++) {
                    float* cx = acc[mi * 4 + ni];
                    // hi * hi
                    asm volatile(
                        "mma.sync.aligned.m16n8k8.row.col.f32.tf32.tf32.f32 "
                        "{%0,%1,%2,%3},{%4,%5,%6,%7},{%8,%9},{%0,%1,%2,%3};\n"
                        : "+f"(cx[0]), "+f"(cx[1]), "+f"(cx[2]), "+f"(cx[3])
                        : "r"(__float_as_uint(ah[0])), "r"(__float_as_uint(ah[1])),
                          "r"(__float_as_uint(ah[2])), "r"(__float_as_uint(ah[3])),
                          "r"(__float_as_uint(bh[ni][0])), "r"(__float_as_uint(bh[ni][1])));
                    // hi * lo
                    asm volatile(
                        "mma.sync.aligned.m16n8k8.row.col.f32.tf32.tf32.f32 "
                        "{%0,%1,%2,%3},{%4,%5,%6,%7},{%8,%9},{%0,%1,%2,%3};\n"
                        : "+f"(cx[0]), "+f"(cx[1]), "+f"(cx[2]), "+f"(cx[3])
                        : "r"(__float_as_uint(ah[0])), "r"(__float_as_uint(ah[1])),
                          "r"(__float_as_uint(ah[2])), "r"(__float_as_uint(ah[3])),
                          "r"(__float_as_uint(bl[ni][0])), "r"(__float_as_uint(bl[ni][1])));
                    // lo * hi
                    asm volatile(
                        "mma.sync.aligned.m16n8k8.row.col.f32.tf32.tf32.f32 "
                        "{%0,%1,%2,%3},{%4,%5,%6,%7},{%8,%9},{%0,%1,%2,%3};\n"
                        : "+f"(cx[0]), "+f"(cx[1]), "+f"(cx[2]), "+f"(cx[3])
                        : "r"(__float_as_uint(al[0])), "r"(__float_as_uint(al[1])),
                          "r"(__float_as_uint(al[2])), "r"(__float_as_uint(al[3])),
                          "r"(__float_as_uint(bh[ni][0])), "r"(__float_as_uint(bh[ni][1])));
                }
            }
        }
        buf ^= 1;
    }

    // epilogue: direct float2 stores
    #pragma unroll
    for (int mi = 0; mi < 4; mi++) {
        #pragma unroll
        for (int ni = 0; ni < 4; ni++) {
            int m = m0 + wm * 64 + mi * 16 + g;
            int n = n0 + wn * 32 + ni * 8 + t2;
            float* cx = acc[mi * 4 + ni];
            float* p = Cc + (size_t)m * L3 + n;
            *(float2*)p            = make_float2(cx[0], cx[1]);
            *(float2*)(p + 8 * L3) = make_float2(cx[2], cx[3]);
        }
    }
}

// ---------------- 5) shifted-sum + max/argmax over lk ------------------------
__global__ void maxarg_kernel(float* __restrict__ outS) {
    int b = blockIdx.y, lq = blockIdx.x;
    int yq = lq / H3, xq = lq % H3;
    const float* base = g_P + (size_t)b * L3 * L3;

    int  rowOff[9];
    bool qv[9];
    #pragma unroll
    for (int t = 0; t < 9; t++) {
        int di = t / 3 - 1, dj = t % 3 - 1;
        int y2 = yq + di, x2 = xq + dj;
        bool v = ((unsigned)y2 < H3) && ((unsigned)x2 < H3);
        qv[t] = v;
        int d = di * H3 + dj;
        rowOff[t] = v ? (lq + d) * L3 + d : 0;
    }
    const float* rnk = &g_nrm[1][b * L3];   // reciprocal key norms

    float best = -1e30f; int bi = 0;
    for (int lk = threadIdx.x; lk < L3; lk += 256) {
        int yk = lk / H3, xk = lk % H3;
        float s = 0.f;
        #pragma unroll
        for (int t = 0; t < 9; t++) {
            int di = t / 3 - 1, dj = t % 3 - 1;
            if (qv[t] && ((unsigned)(yk + di) < H3) && ((unsigned)(xk + dj) < H3))
                s += base[rowOff[t] + lk];
        }
        float sc = s * rnk[lk];
        if (sc > best) { best = sc; bi = lk; }
    }

    __shared__ float sv[256];
    __shared__ int   si[256];
    sv[threadIdx.x] = best; si[threadIdx.x] = bi;
    __syncthreads();
    for (int st = 128; st > 0; st >>= 1) {
        if (threadIdx.x < st) {
            float o = sv[threadIdx.x + st]; int oi = si[threadIdx.x + st];
            if (o > sv[threadIdx.x] || (o == sv[threadIdx.x] && oi < si[threadIdx.x])) {
                sv[threadIdx.x] = o; si[threadIdx.x] = oi;
            }
        }
        __syncthreads();
    }
    if (threadIdx.x == 0) {
        g_idx[b * L3 + lq] = si[0];
        outS[b * L3 + lq]  = sv[0] / g_nrm[0][b * L3 + lq];
    }
}

// ---------------- 6) fused gather + fold-normalize ---------------------------
__global__ void transfer_kernel(float* __restrict__ out, int C, int W, int s, int sel) {
    const float* clT = (sel == 0) ? g_cl3T : (sel == 1) ? g_cl2T : g_cl1T;
    __shared__ float acc[12288];                 // C*W floats == 48KB for all levels
    int b = blockIdx.y, y = blockIdx.x;
    int tid = threadIdx.x;
    int cid  = tid % C;
    int xsub = tid / C;
    int ppp  = 256 / C;                          // pixels handled in parallel

    int tyq = y / s;
    int yqs[3]; int nvy = 0;
    #pragma unroll
    for (int d = -1; d <= 1; d++) {
        int yq = tyq + d;
        if (0 <= yq && yq < H3) yqs[nvy++] = yq;
    }
    const int* idxb = g_idx + b * L3;
    size_t clb = (size_t)b * W * W * C;

    for (int x0 = 0; x0 < W; x0 += ppp) {
        int x = x0 + xsub;
        int txq = x / s;
        float sum = 0.f; int cnt = 0;
        for (int a = 0; a < nvy; a++) {
            int yq = yqs[a];
            #pragma unroll
            for (int d = -1; d <= 1; d++) {
                int xq = txq + d;
                if ((unsigned)xq >= H3) continue;
                cnt++;
                int idx = idxb[yq * H3 + xq];
                int yk = idx / H3, xk = idx % H3;
                int ys = y + s * (yk - yq);
                int xs = x + s * (xk - xq);
                if ((unsigned)ys < (unsigned)W && (unsigned)xs < (unsigned)W)
                    sum += clT[clb + ((size_t)ys * W + xs) * C + cid];
            }
        }
        acc[cid * W + x] = sum / (float)cnt;
    }
    __syncthreads();

    size_t ob = (size_t)b * C * W * W + (size_t)y * W;
    for (int i = tid; i < C * W; i += 256) {
        int c = i / W, x = i % W;
        out[ob + (size_t)c * W * W + x] = acc[i];
    }
}

// ---------------- launch ------------------------------------------------------
extern "C" void kernel_launch(void* const* d_in, const int* in_sizes, int n_in,
                              void* d_out, int out_size) {
    const float* img = (const float*)d_in[0];   // dh_img_lv3 [4,256,48,48]
    const float* ref = (const float*)d_in[1];   // dh_ref_lv3 [4,256,48,48]
    const float* cl1 = (const float*)d_in[2];   // cl_ref_lv1 [4,64,192,192]
    const float* cl2 = (const float*)d_in[3];   // cl_ref_lv2 [4,128,96,96]
    const float* cl3 = (const float*)d_in[4];   // cl_ref_lv3 [4,256,48,48]

    float* outS  = (float*)d_out;               // [4,1,48,48]
    float* outT3 = outS  + BB * L3;             // [4,256,48,48]
    float* outT2 = outT3 + (size_t)BB * C3 * L3;    // [4,128,96,96]
    float* outT1 = outT2 + (size_t)BB * C2 * L2n;   // [4,64,192,192]

    sqsum_kernel  <<<dim3(9, BB, 2), 256>>>(img, ref);          // launch 0
    boxnorm_kernel<<<dim3(9, BB, 2), 256>>>();                  // launch 1

    transpose_kernel<<<dim3(L3  / 32, C3 / 32, BB), dim3(32, 8)>>>(cl3, C3, L3,  0);  // 2
    transpose_kernel<<<dim3(L2n / 32, C2 / 32, BB), dim3(32, 8)>>>(cl2, C2, L2n, 1);  // 3
    transpose_kernel<<<dim3(L1n / 32, C1 / 32, BB), dim3(32, 8)>>>(cl1, C1, L1n, 2);  // 4

    gemm_tf32_kernel<<<dim3(L3 / 128, L3 / 128, BB), 256>>>(img, ref);                // 5 (profiled)

    maxarg_kernel<<<dim3(L3, BB), 256>>>(outS);

    transfer_kernel<<<dim3(H3, BB), 256>>>(outT3, C3, H3, 1, 0);
    transfer_kernel<<<dim3(H2, BB), 256>>>(outT2, C2, H2, 2, 1);
    transfer_kernel<<<dim3(H1, BB), 256>>>(outT1, C1, H1, 4, 2);
}